// round 7
// baseline (speedup 1.0000x reference)
#include <cuda_runtime.h>
#include <stdint.h>

// EmbeddingDropout: out[r, :] = weight[x[r], :] * mask[x[r]]
// x: [16384] int32, weight: [50257, 512] f32, mask: [50257] f32.
//
// R7: one warp per row. Weight loads use 256-bit ld.global.nc with
// L2::evict_last (sm_103a requires v8.b32 for the evict-policy form —
// also halves read wavefronts). Output stores are st.global.cs v4
// (evict-first) so the write-once stream doesn't churn the pinned
// ~29 MB gather set, which stays L2-resident across graph replays.

#define D 512
#define D4 (D / 4)            // 128 float4 per row
#define THREADS 256           // 8 warps -> 8 rows per block
#define ROWS_PER_BLOCK (THREADS / 32)

struct f32x8 { float v[8]; };

__device__ __forceinline__ f32x8 ldg256_evict_last(const void* p) {
    f32x8 r;
    asm volatile(
        "ld.global.nc.L2::evict_last.v8.f32 {%0,%1,%2,%3,%4,%5,%6,%7}, [%8];"
        : "=f"(r.v[0]), "=f"(r.v[1]), "=f"(r.v[2]), "=f"(r.v[3]),
          "=f"(r.v[4]), "=f"(r.v[5]), "=f"(r.v[6]), "=f"(r.v[7])
        : "l"(p));
    return r;
}

__device__ __forceinline__ void stg_cs_v4(void* p, float a, float b, float c, float d) {
    asm volatile("st.global.cs.v4.f32 [%0], {%1,%2,%3,%4};"
                 :: "l"(p), "f"(a), "f"(b), "f"(c), "f"(d)
                 : "memory");
}

__global__ __launch_bounds__(THREADS) void embedding_dropout_kernel(
    const int* __restrict__ x,            // [N]
    const float* __restrict__ weight,     // [V, D]
    const float* __restrict__ mask,       // [V]
    float* __restrict__ out,              // [N, D]
    int n_rows)
{
    int row  = (blockIdx.x * THREADS + threadIdx.x) >> 5;  // one warp per row
    int lane = threadIdx.x & 31;
    if (row >= n_rows) return;

    int idx = __ldg(&x[row]);             // broadcast across the warp
    float s = __ldg(&mask[idx]);

    const float* wrow = weight + (size_t)idx * D + lane * 8;
    float*       orow = out    + (size_t)row * D + lane * 8;

    // Two independent 32B loads per thread: covers 2 * 32 * 8 = 512 floats.
    f32x8 a = ldg256_evict_last(wrow);
    f32x8 b = ldg256_evict_last(wrow + 32 * 8);

    #pragma unroll
    for (int i = 0; i < 8; i++) { a.v[i] *= s; b.v[i] *= s; }

    stg_cs_v4(orow,              a.v[0], a.v[1], a.v[2], a.v[3]);
    stg_cs_v4(orow + 4,          a.v[4], a.v[5], a.v[6], a.v[7]);
    stg_cs_v4(orow + 32 * 8,     b.v[0], b.v[1], b.v[2], b.v[3]);
    stg_cs_v4(orow + 32 * 8 + 4, b.v[4], b.v[5], b.v[6], b.v[7]);
}

extern "C" void kernel_launch(void* const* d_in, const int* in_sizes, int n_in,
                              void* d_out, int out_size)
{
    // Identify inputs by element count: x=16384, weight=25731584, mask=50257.
    long long max_sz = -1, mid_sz = -1;
    int wi = -1, mi = -1, xi = -1;
    for (int i = 0; i < n_in; i++)
        if (in_sizes[i] > max_sz) { max_sz = in_sizes[i]; wi = i; }
    for (int i = 0; i < n_in; i++)
        if (i != wi && in_sizes[i] > mid_sz) { mid_sz = in_sizes[i]; mi = i; }
    for (int i = 0; i < n_in; i++)
        if (i != wi && i != mi) { xi = i; break; }

    const int*   x    = (const int*)d_in[xi];
    const float* w    = (const float*)d_in[wi];
    const float* mask = (const float*)d_in[mi];
    float*       out  = (float*)d_out;
    int n_rows = in_sizes[xi];

    int blocks = (n_rows + ROWS_PER_BLOCK - 1) / ROWS_PER_BLOCK;
    embedding_dropout_kernel<<<blocks, THREADS>>>(x, w, mask, out, n_rows);
}